// round 14
// baseline (speedup 1.0000x reference)
#include <cuda_runtime.h>
#include <cuda_bf16.h>
#include <math.h>
#include <cstdint>

#define NN 200000
#define NUM_BAGS 25000
#define DD 690
#define PAIRS 345       // DD/2 float2 pairs
#define RR 53
#define MAX_BAG 256
#define NTILES 7        // ceil(53/8) n8-tiles
#define KT_COUNT 44     // ceil(690/16) k16-steps
#define PCOLS 64        // padded P row width

// P = repre @ rel^T, rows padded to 64 (cols 56..63 stay zero: static init, never written)
__device__ float g_P[(size_t)NN * PCOLS];                 // 51.2 MB
// B in fragment-major layout: [ntile][kt][lane][4] = {bh(p), bl(p), bh(p+4), bl(p+4)}
__device__ uint32_t g_rel_fr[(size_t)NTILES * KT_COUNT * 32 * 4];

__device__ __forceinline__ int sniff_is64(const void* scope)
{
    // scope row0 = (start0=0, end0>=1). int32 layout: w[1]=end0>=1 ; int64: w[1]=0
    return (((const int*)scope)[1] == 0) ? 1 : 0;
}

__device__ __forceinline__ int load_idx(const void* p, int i, int is64)
{
    return is64 ? (int)((const long long*)p)[i] : ((const int*)p)[i];
}

__device__ __forceinline__ uint32_t smem_u32(const void* p)
{
    uint32_t addr;
    asm("{ .reg .u64 tmp; cvta.to.shared.u64 tmp, %1; cvt.u32.u64 %0, tmp; }"
        : "=r"(addr) : "l"(p));
    return addr;
}

__device__ __forceinline__ uint32_t bf16x2_split_hi(float v0, float v1, uint32_t* lo)
{
    __nv_bfloat16 h0 = __float2bfloat16(v0);
    __nv_bfloat16 h1 = __float2bfloat16(v1);
    __nv_bfloat16 l0 = __float2bfloat16(v0 - __bfloat162float(h0));
    __nv_bfloat16 l1 = __float2bfloat16(v1 - __bfloat162float(h1));
    __nv_bfloat162 hh; hh.x = h0; hh.y = h1;
    __nv_bfloat162 ll; ll.x = l0; ll.y = l1;
    *lo = *reinterpret_cast<uint32_t*>(&ll);
    return *reinterpret_cast<uint32_t*>(&hh);
}

// ---------------------------------------------------------------------------
// rel prep (exact R13): fragment-major B.
// ---------------------------------------------------------------------------
__global__ void rel_prep_kernel(const float* __restrict__ relp)
{
    const int e = blockIdx.x * blockDim.x + threadIdx.x;
    if (e >= NTILES * KT_COUNT * 32) return;
    const int nt   = e / (KT_COUNT * 32);
    const int rem  = e % (KT_COUNT * 32);
    const int kt   = rem >> 5;
    const int lane = rem & 31;
    const int gid  = lane >> 2;
    const int tig  = lane & 3;
    const int n    = nt * 8 + gid;
    const int p1   = 8 * kt + tig;
    const int p2   = p1 + 4;

    float a0 = 0.0f, a1 = 0.0f, b0 = 0.0f, b1 = 0.0f;
    if (n < RR) {
        if (2 * p1 < DD)     a0 = relp[(size_t)n * DD + 2 * p1];
        if (2 * p1 + 1 < DD) a1 = relp[(size_t)n * DD + 2 * p1 + 1];
        if (2 * p2 < DD)     b0 = relp[(size_t)n * DD + 2 * p2];
        if (2 * p2 + 1 < DD) b1 = relp[(size_t)n * DD + 2 * p2 + 1];
    }
    uint32_t lo1, lo2;
    const uint32_t hi1 = bf16x2_split_hi(a0, a1, &lo1);
    const uint32_t hi2 = bf16x2_split_hi(b0, b1, &lo2);
    uint4 v; v.x = hi1; v.y = lo1; v.z = hi2; v.w = lo2;
    *reinterpret_cast<uint4*>(g_rel_fr + (size_t)e * 4) = v;
}

// ---------------------------------------------------------------------------
// K_P: P = repre @ rel^T  (M=200000, N=56, K=690) via HMMA bf16 2-split 3-term.
// BM=128, 256 threads: warp w owns m16 block w (0..7), all 7 n-tiles.
// A staging: 128 rows x 16 k per kt, fp32 LDG.64 -> hi/lo bf16 smem tiles
// (row stride 12 u32 = 48B: LDSM-conflict-free, 16B-aligned). Double-buffered.
// ---------------------------------------------------------------------------
#define MMA16816(c0, c1, c2, c3, a0, a1, a2, a3, b0, b1) \
    asm volatile("mma.sync.aligned.m16n8k16.row.col.f32.bf16.bf16.f32 " \
        "{%0,%1,%2,%3}, {%4,%5,%6,%7}, {%8,%9}, {%0,%1,%2,%3};" \
        : "+f"(c0), "+f"(c1), "+f"(c2), "+f"(c3) \
        : "r"(a0), "r"(a1), "r"(a2), "r"(a3), "r"(b0), "r"(b1))

#define LDSM_X4(r0, r1, r2, r3, addr) \
    asm volatile("ldmatrix.sync.aligned.m8n8.x4.shared.b16 {%0,%1,%2,%3}, [%4];" \
        : "=r"(r0), "=r"(r1), "=r"(r2), "=r"(r3) : "r"(addr))

#define ROWSTRIDE 12

__global__ __launch_bounds__(256) void pgemm_kernel(
    const float* __restrict__ repre)
{
    __shared__ __align__(16) uint32_t sAhi[2][128 * ROWSTRIDE];
    __shared__ __align__(16) uint32_t sAlo[2][128 * ROWSTRIDE];

    const int tid  = threadIdx.x;
    const int wid  = tid >> 5;      // 0..7 = m16 block
    const int lane = tid & 31;
    const int gid  = lane >> 2;
    const int tig  = lane & 3;

    const int m0 = blockIdx.x * 128;

    // staging coords: thread -> (row = tid>>1, half = tid&1), 4 float2 each
    const int srow = tid >> 1;          // 0..127
    const int shalf = tid & 1;          // 0 or 1 (pairs half*4 .. half*4+3)
    int mrow_ld = m0 + srow;
    if (mrow_ld >= NN) mrow_ld = NN - 1;    // clamp (dup read, stores guarded)
    const float2* __restrict__ aptr = (const float2*)(repre + (size_t)mrow_ld * DD);
    const int sidx = srow * ROWSTRIDE + shalf * 4;

    // LDSM addressing (proven R13 layout)
    const int arow  = 16 * wid + (lane & 15);
    const int acol  = (lane < 16) ? 0 : 4;
    const uint32_t a_off = (uint32_t)(arow * ROWSTRIDE + acol) * 4u;
    const uint32_t ahi_base = smem_u32(&sAhi[0][0]);
    const uint32_t alo_base = smem_u32(&sAlo[0][0]);
    const uint32_t bufstride = 128 * ROWSTRIDE * 4u;

    float c[NTILES][4];
    #pragma unroll
    for (int t = 0; t < NTILES; t++)
        #pragma unroll
        for (int q = 0; q < 4; q++) c[t][q] = 0.0f;

    float2 va[4];

    auto load_a = [&](int kt) {
        #pragma unroll
        for (int q = 0; q < 4; q++) {
            const int p = 8 * kt + shalf * 4 + q;
            va[q] = (p < PAIRS) ? aptr[p] : make_float2(0.0f, 0.0f);
        }
    };
    auto store_a = [&](int bufn) {
        uint32_t hi[4], lo[4];
        #pragma unroll
        for (int q = 0; q < 4; q++)
            hi[q] = bf16x2_split_hi(va[q].x, va[q].y, &lo[q]);
        *(uint2*)&sAhi[bufn][sidx]     = make_uint2(hi[0], hi[1]);
        *(uint2*)&sAhi[bufn][sidx + 2] = make_uint2(hi[2], hi[3]);
        *(uint2*)&sAlo[bufn][sidx]     = make_uint2(lo[0], lo[1]);
        *(uint2*)&sAlo[bufn][sidx + 2] = make_uint2(lo[2], lo[3]);
    };

    load_a(0);
    store_a(0);
    __syncthreads();

    int buf = 0;
    for (int kt = 0; kt < KT_COUNT; kt++) {
        const bool more = (kt + 1 < KT_COUNT);
        if (more) load_a(kt + 1);

        uint32_t ah0, ah1, ah2, ah3, al0, al1, al2, al3;
        LDSM_X4(ah0, ah1, ah2, ah3, ahi_base + buf * bufstride + a_off);
        LDSM_X4(al0, al1, al2, al3, alo_base + buf * bufstride + a_off);

        #pragma unroll
        for (int t = 0; t < NTILES; t++) {
            const uint4 bv = *(const uint4*)(g_rel_fr +
                (size_t)((t * KT_COUNT + kt) * 32 + lane) * 4);
            MMA16816(c[t][0], c[t][1], c[t][2], c[t][3],
                     ah0, ah1, ah2, ah3, bv.x, bv.z);
            MMA16816(c[t][0], c[t][1], c[t][2], c[t][3],
                     ah0, ah1, ah2, ah3, bv.y, bv.w);
            MMA16816(c[t][0], c[t][1], c[t][2], c[t][3],
                     al0, al1, al2, al3, bv.x, bv.z);
        }

        if (more) store_a(buf ^ 1);
        __syncthreads();
        buf ^= 1;
    }

    // epilogue: c[t][0]=(r0,n), [1]=(r0,n+1), [2]=(r1,n), [3]=(r1,n+1)
    const int r0 = m0 + 16 * wid + gid;
    const int r1 = r0 + 8;
    #pragma unroll
    for (int t = 0; t < NTILES; t++) {
        const int n = t * 8 + 2 * tig;   // even, < 56
        if (r0 < NN) *(float2*)&g_P[(size_t)r0 * PCOLS + n] = make_float2(c[t][0], c[t][1]);
        if (r1 < NN) *(float2*)&g_P[(size_t)r1 * PCOLS + n] = make_float2(c[t][2], c[t][3]);
    }
}

// ---------------------------------------------------------------------------
// K_bag: warp per bag. Gather rel_logits from P, softmax, weighted sum of
// P rows (53 cols) + bias.  8 warps/CTA.
// ---------------------------------------------------------------------------
__global__ __launch_bounds__(256) void bag_out_kernel(
    const void*  __restrict__ scope,
    const void*  __restrict__ labels,
    const float* __restrict__ bias,
    float* __restrict__ out)
{
    __shared__ float sw[8][MAX_BAG];

    const int tid  = threadIdx.x;
    const int wid  = tid >> 5;
    const int lane = tid & 31;
    const int b    = blockIdx.x * 8 + wid;
    if (b >= NUM_BAGS) return;

    const int is64 = sniff_is64(scope);
    int start = load_idx(scope, 2 * b, is64);
    int end   = load_idx(scope, 2 * b + 1, is64);
    if (start < 0) start = 0;
    if (start > NN) start = NN;
    if (end < start) end = start;
    if (end > NN) end = NN;
    int nb = end - start;
    if (nb > MAX_BAG) nb = MAX_BAG;

    // gather per-instance logits P[i, labels[i]]
    for (int j = lane; j < nb; j += 32) {
        const int i = start + j;
        int lab = load_idx(labels, i, is64);
        if (lab < 0) lab = 0;
        if (lab >= RR) lab = RR - 1;
        sw[wid][j] = g_P[(size_t)i * PCOLS + lab];
    }
    __syncwarp();

    float m = -INFINITY;
    for (int j = lane; j < nb; j += 32) m = fmaxf(m, sw[wid][j]);
    #pragma unroll
    for (int o = 16; o > 0; o >>= 1)
        m = fmaxf(m, __shfl_xor_sync(0xffffffffu, m, o));

    float s = 0.0f;
    for (int j = lane; j < nb; j += 32) {
        const float e = expf(sw[wid][j] - m);
        sw[wid][j] = e;
        s += e;
    }
    #pragma unroll
    for (int o = 16; o > 0; o >>= 1)
        s += __shfl_xor_sync(0xffffffffu, s, o);
    const float inv = 1.0f / s;
    __syncwarp();

    // weighted sum of P rows: lane owns cols 2*lane, 2*lane+1
    float2 acc = make_float2(0.0f, 0.0f);
    int j = 0;
    for (; j + 3 < nb; j += 4) {
        const float w0 = sw[wid][j],     w1 = sw[wid][j + 1];
        const float w2 = sw[wid][j + 2], w3 = sw[wid][j + 3];
        const float2 v0 = ((const float2*)(g_P + (size_t)(start + j    ) * PCOLS))[lane];
        const float2 v1 = ((const float2*)(g_P + (size_t)(start + j + 1) * PCOLS))[lane];
        const float2 v2 = ((const float2*)(g_P + (size_t)(start + j + 2) * PCOLS))[lane];
        const float2 v3 = ((const float2*)(g_P + (size_t)(start + j + 3) * PCOLS))[lane];
        acc.x = fmaf(w0, v0.x, acc.x); acc.y = fmaf(w0, v0.y, acc.y);
        acc.x = fmaf(w1, v1.x, acc.x); acc.y = fmaf(w1, v1.y, acc.y);
        acc.x = fmaf(w2, v2.x, acc.x); acc.y = fmaf(w2, v2.y, acc.y);
        acc.x = fmaf(w3, v3.x, acc.x); acc.y = fmaf(w3, v3.y, acc.y);
    }
    for (; j < nb; j++) {
        const float w = sw[wid][j];
        const float2 v = ((const float2*)(g_P + (size_t)(start + j) * PCOLS))[lane];
        acc.x = fmaf(w, v.x, acc.x);
        acc.y = fmaf(w, v.y, acc.y);
    }

    const int n0 = 2 * lane;
    const int n1 = n0 + 1;
    if (n0 < RR) out[(size_t)b * RR + n0] = acc.x * inv + bias[n0];
    if (n1 < RR) out[(size_t)b * RR + n1] = acc.y * inv + bias[n1];
}

extern "C" void kernel_launch(void* const* d_in, const int* in_sizes, int n_in,
                              void* d_out, int out_size)
{
    const float* repre  = (const float*)d_in[0];
    const float* relmat = (const float*)d_in[1];
    const float* bias   = (const float*)d_in[2];
    const void*  scope  = d_in[3];
    const void*  labels = d_in[4];
    float* out = (float*)d_out;

    rel_prep_kernel<<<(NTILES * KT_COUNT * 32 + 127) / 128, 128>>>(relmat);
    pgemm_kernel<<<(NN + 127) / 128, 256>>>(repre);
    bag_out_kernel<<<(NUM_BAGS + 7) / 8, 256>>>(scope, labels, bias, out);
}

// round 15
// speedup vs baseline: 1.3556x; 1.3556x over previous
#include <cuda_runtime.h>
#include <cuda_bf16.h>
#include <math.h>
#include <cstdint>

#define NN 200000
#define NUM_BAGS 25000
#define DD 690
#define D2 345          // DD/2 float2s
#define RR 53
#define MAX_BAG 256
#define CROWS 12        // bag rows cached in smem (avg bag = 8)
#define KPAD 704        // DD padded to 44*16
#define NTILES 7        // ceil(53/8) n8-tiles

// Interleaved (hi,lo) bf16x2 storage (R13): u32 col 2c = hi pair, 2c+1 = lo pair.
__device__ uint32_t g_att_hl[(size_t)NUM_BAGS * KPAD];   // 70.4 MB
// B in fragment-major layout: [ntile][kt][lane][4] = {bh(p), bl(p), bh(p+4), bl(p+4)}
__device__ uint32_t g_rel_fr[(size_t)NTILES * 44 * 32 * 4];

__device__ __forceinline__ int sniff_is64(const void* scope)
{
    return (((const int*)scope)[1] == 0) ? 1 : 0;
}

__device__ __forceinline__ int load_idx(const void* p, int i, int is64)
{
    return is64 ? (int)((const long long*)p)[i] : ((const int*)p)[i];
}

__device__ __forceinline__ uint32_t smem_u32(const void* p)
{
    uint32_t addr;
    asm("{ .reg .u64 tmp; cvta.to.shared.u64 tmp, %1; cvt.u32.u64 %0, tmp; }"
        : "=r"(addr) : "l"(p));
    return addr;
}

__device__ __forceinline__ void store_hl(uint32_t* __restrict__ row, int f, float2 v)
{
    __nv_bfloat16 hx = __float2bfloat16(v.x);
    __nv_bfloat16 hy = __float2bfloat16(v.y);
    __nv_bfloat16 lx = __float2bfloat16(v.x - __bfloat162float(hx));
    __nv_bfloat16 ly = __float2bfloat16(v.y - __bfloat162float(hy));
    __nv_bfloat162 hh; hh.x = hx; hh.y = hy;
    __nv_bfloat162 ll; ll.x = lx; ll.y = ly;
    row[2 * f]     = *reinterpret_cast<uint32_t*>(&hh);
    row[2 * f + 1] = *reinterpret_cast<uint32_t*>(&ll);
}

__device__ __forceinline__ uint32_t bf16x2_split_hi(float v0, float v1, uint32_t* lo)
{
    __nv_bfloat16 h0 = __float2bfloat16(v0);
    __nv_bfloat16 h1 = __float2bfloat16(v1);
    __nv_bfloat16 l0 = __float2bfloat16(v0 - __bfloat162float(h0));
    __nv_bfloat16 l1 = __float2bfloat16(v1 - __bfloat162float(h1));
    __nv_bfloat162 hh; hh.x = h0; hh.y = h1;
    __nv_bfloat162 ll; ll.x = l0; ll.y = l1;
    *lo = *reinterpret_cast<uint32_t*>(&ll);
    return *reinterpret_cast<uint32_t*>(&hh);
}

// ---------------------------------------------------------------------------
// rel prep (exact R13): fragment-major B.
// ---------------------------------------------------------------------------
__global__ void rel_prep_kernel(const float* __restrict__ relp)
{
    const int e = blockIdx.x * blockDim.x + threadIdx.x;
    if (e >= NTILES * 44 * 32) return;
    const int nt   = e / (44 * 32);
    const int rem  = e % (44 * 32);
    const int kt   = rem >> 5;
    const int lane = rem & 31;
    const int gid  = lane >> 2;
    const int tig  = lane & 3;
    const int n    = nt * 8 + gid;
    const int p1   = 8 * kt + tig;
    const int p2   = p1 + 4;

    float a0 = 0.0f, a1 = 0.0f, b0 = 0.0f, b1 = 0.0f;
    if (n < RR) {
        if (2 * p1 < DD)     a0 = relp[(size_t)n * DD + 2 * p1];
        if (2 * p1 + 1 < DD) a1 = relp[(size_t)n * DD + 2 * p1 + 1];
        if (2 * p2 < DD)     b0 = relp[(size_t)n * DD + 2 * p2];
        if (2 * p2 + 1 < DD) b1 = relp[(size_t)n * DD + 2 * p2 + 1];
    }
    uint32_t lo1, lo2;
    const uint32_t hi1 = bf16x2_split_hi(a0, a1, &lo1);
    const uint32_t hi2 = bf16x2_split_hi(b0, b1, &lo2);
    uint4 v; v.x = hi1; v.y = lo1; v.z = hi2; v.w = lo2;
    *reinterpret_cast<uint4*>(g_rel_fr + (size_t)e * 4) = v;
}

// ---------------------------------------------------------------------------
// K1: block per bag, 128 threads. R13 structure + smem row-cache: the first
// CROWS rows of each bag are stored to smem during phase 1 (they're already
// register-resident in the dot loop), so phase 3 reads them via LDS instead
// of re-reading global.
// ---------------------------------------------------------------------------
__global__ __launch_bounds__(128, 6) void bag_attn_kernel(
    const float* __restrict__ repre,
    const float* __restrict__ rel,
    const void*  __restrict__ scope,
    const void*  __restrict__ labels)
{
    __shared__ float2 s_x[CROWS][D2];    // 33.1 KB row cache
    __shared__ float  s_rl[MAX_BAG];
    __shared__ float  s_w[MAX_BAG];

    const int tid  = threadIdx.x;
    const int wid  = tid >> 5;
    const int lane = tid & 31;
    const int is64 = sniff_is64(scope);

    const int b = blockIdx.x;
    int start = load_idx(scope, 2 * b, is64);
    int end   = load_idx(scope, 2 * b + 1, is64);
    if (start < 0) start = 0;
    if (start > NN) start = NN;
    if (end < start) end = start;
    if (end > NN) end = NN;
    int nb = end - start;
    if (nb > MAX_BAG) nb = MAX_BAG;

    int mylab = 0;
    {
        const int j = wid + 4 * lane;
        if (j < nb) {
            int lab = load_idx(labels, start + j, is64);
            if (lab < 0) lab = 0;
            if (lab >= RR) lab = RR - 1;
            mylab = lab;
        }
    }

    // ---- phase 1: per-instance logits (warp per instance) + row cache ----
    for (int k = 0; ; k++) {
        const int j = wid + 4 * k;
        if (j >= nb) break;
        int lab;
        if (k < 32) {
            lab = __shfl_sync(0xffffffffu, mylab, k);
        } else {
            lab = load_idx(labels, start + j, is64);
            if (lab < 0) lab = 0;
            if (lab >= RR) lab = RR - 1;
        }
        const float2* __restrict__ xr2 = (const float2*)(repre + (size_t)(start + j) * DD);
        const float2* __restrict__ rr2 = (const float2*)(rel + (size_t)lab * DD);
        const bool docache = (j < CROWS);
        float acc = 0.0f;
        #pragma unroll
        for (int it = 0; it < 10; it++) {
            const int d = lane + 32 * it;
            const float2 x = xr2[d];
            const float2 r = rr2[d];
            if (docache) s_x[j][d] = x;
            acc = fmaf(x.x, r.x, acc);
            acc = fmaf(x.y, r.y, acc);
        }
        {
            const int d = 320 + lane;
            if (d < D2) {
                const float2 x = xr2[d];
                const float2 r = rr2[d];
                if (docache) s_x[j][d] = x;
                acc = fmaf(x.x, r.x, acc);
                acc = fmaf(x.y, r.y, acc);
            }
        }
        #pragma unroll
        for (int o = 16; o > 0; o >>= 1)
            acc += __shfl_xor_sync(0xffffffffu, acc, o);
        if (lane == 0) s_rl[j] = acc;
    }
    __syncthreads();

    // ---- phase 2: softmax ----
    const bool fast = (nb <= 32);
    float wreg = 0.0f;
    if (fast) {
        float t = (lane < nb) ? s_rl[lane] : -INFINITY;
        float m = t;
        #pragma unroll
        for (int o = 16; o > 0; o >>= 1)
            m = fmaxf(m, __shfl_xor_sync(0xffffffffu, m, o));
        float e = (lane < nb) ? expf(t - m) : 0.0f;
        float s = e;
        #pragma unroll
        for (int o = 16; o > 0; o >>= 1)
            s += __shfl_xor_sync(0xffffffffu, s, o);
        wreg = e / s;
    } else {
        if (wid == 0) {
            float m = -INFINITY;
            for (int j = lane; j < nb; j += 32) m = fmaxf(m, s_rl[j]);
            #pragma unroll
            for (int o = 16; o > 0; o >>= 1)
                m = fmaxf(m, __shfl_xor_sync(0xffffffffu, m, o));
            float s = 0.0f;
            for (int j = lane; j < nb; j += 32) {
                float e = expf(s_rl[j] - m);
                s_w[j] = e;
                s += e;
            }
            #pragma unroll
            for (int o = 16; o > 0; o >>= 1)
                s += __shfl_xor_sync(0xffffffffu, s, o);
            float inv = 1.0f / s;
            for (int j = lane; j < nb; j += 32) s_w[j] *= inv;
        }
        __syncthreads();
    }

    // ---- phase 3: weighted bag sum (cached rows via LDS, rest via LDG) ----
    const int f0 = tid;
    const int f1 = tid + 128;
    const int f2 = tid + 256;
    const bool has2 = (f2 < D2);
    float2 a0 = make_float2(0.0f, 0.0f);
    float2 a1 = make_float2(0.0f, 0.0f);
    float2 a2 = make_float2(0.0f, 0.0f);

    const int ncache = (nb < CROWS) ? nb : CROWS;
    int j = 0;
    for (; j + 1 < ncache; j += 2) {
        const float w0 = fast ? __shfl_sync(0xffffffffu, wreg, j & 31) : s_w[j];
        const float w1 = fast ? __shfl_sync(0xffffffffu, wreg, (j + 1) & 31) : s_w[j + 1];
        const float2 v00 = s_x[j][f0],     v10 = s_x[j + 1][f0];
        const float2 v01 = s_x[j][f1],     v11 = s_x[j + 1][f1];
        a0.x = fmaf(w0, v00.x, a0.x); a0.y = fmaf(w0, v00.y, a0.y);
        a0.x = fmaf(w1, v10.x, a0.x); a0.y = fmaf(w1, v10.y, a0.y);
        a1.x = fmaf(w0, v01.x, a1.x); a1.y = fmaf(w0, v01.y, a1.y);
        a1.x = fmaf(w1, v11.x, a1.x); a1.y = fmaf(w1, v11.y, a1.y);
        if (has2) {
            const float2 v02 = s_x[j][f2], v12 = s_x[j + 1][f2];
            a2.x = fmaf(w0, v02.x, a2.x); a2.y = fmaf(w0, v02.y, a2.y);
            a2.x = fmaf(w1, v12.x, a2.x); a2.y = fmaf(w1, v12.y, a2.y);
        }
    }
    for (; j < ncache; j++) {
        const float w = fast ? __shfl_sync(0xffffffffu, wreg, j & 31) : s_w[j];
        const float2 v0 = s_x[j][f0];
        const float2 v1 = s_x[j][f1];
        a0.x = fmaf(w, v0.x, a0.x); a0.y = fmaf(w, v0.y, a0.y);
        a1.x = fmaf(w, v1.x, a1.x); a1.y = fmaf(w, v1.y, a1.y);
        if (has2) {
            const float2 v2 = s_x[j][f2];
            a2.x = fmaf(w, v2.x, a2.x); a2.y = fmaf(w, v2.y, a2.y);
        }
    }
    // overflow rows from global (R13 x4-unrolled path)
    for (; j + 3 < nb; j += 4) {
        const float2* __restrict__ x0 = (const float2*)(repre + (size_t)(start + j    ) * DD);
        const float2* __restrict__ x1 = (const float2*)(repre + (size_t)(start + j + 1) * DD);
        const float2* __restrict__ x2 = (const float2*)(repre + (size_t)(start + j + 2) * DD);
        const float2* __restrict__ x3 = (const float2*)(repre + (size_t)(start + j + 3) * DD);
        float w0, w1, w2, w3;
        if (fast) {
            w0 = __shfl_sync(0xffffffffu, wreg, j & 31);
            w1 = __shfl_sync(0xffffffffu, wreg, (j + 1) & 31);
            w2 = __shfl_sync(0xffffffffu, wreg, (j + 2) & 31);
            w3 = __shfl_sync(0xffffffffu, wreg, (j + 3) & 31);
        } else {
            w0 = s_w[j]; w1 = s_w[j + 1]; w2 = s_w[j + 2]; w3 = s_w[j + 3];
        }
        const float2 p00 = __ldcs(&x0[f0]), p10 = __ldcs(&x1[f0]),
                     p20 = __ldcs(&x2[f0]), p30 = __ldcs(&x3[f0]);
        const float2 p01 = __ldcs(&x0[f1]), p11 = __ldcs(&x1[f1]),
                     p21 = __ldcs(&x2[f1]), p31 = __ldcs(&x3[f1]);
        float2 p02, p12, p22, p32;
        if (has2) { p02 = __ldcs(&x0[f2]); p12 = __ldcs(&x1[f2]);
                    p22 = __ldcs(&x2[f2]); p32 = __ldcs(&x3[f2]); }
        a0.x = fmaf(w0, p00.x, a0.x); a0.y = fmaf(w0, p00.y, a0.y);
        a0.x = fmaf(w1, p10.x, a0.x); a0.y = fmaf(w1, p10.y, a0.y);
        a0.x = fmaf(w2, p20.x, a0.x); a0.y = fmaf(w2, p20.y, a0.y);
        a0.x = fmaf(w3, p30.x, a0.x); a0.y = fmaf(w3, p30.y, a0.y);
        a1.x = fmaf(w0, p01.x, a1.x); a1.y = fmaf(w0, p01.y, a1.y);
        a1.x = fmaf(w1, p11.x, a1.x); a1.y = fmaf(w1, p11.y, a1.y);
        a1.x = fmaf(w2, p21.x, a1.x); a1.y = fmaf(w2, p21.y, a1.y);
        a1.x = fmaf(w3, p31.x, a1.x); a1.y = fmaf(w3, p31.y, a1.y);
        if (has2) {
            a2.x = fmaf(w0, p02.x, a2.x); a2.y = fmaf(w0, p02.y, a2.y);
            a2.x = fmaf(w1, p12.x, a2.x); a2.y = fmaf(w1, p12.y, a2.y);
            a2.x = fmaf(w2, p22.x, a2.x); a2.y = fmaf(w2, p22.y, a2.y);
            a2.x = fmaf(w3, p32.x, a2.x); a2.y = fmaf(w3, p32.y, a2.y);
        }
    }
    for (; j < nb; j++) {
        const float2* __restrict__ xA = (const float2*)(repre + (size_t)(start + j) * DD);
        const float wA = fast ? __shfl_sync(0xffffffffu, wreg, j & 31) : s_w[j];
        const float2 v0 = __ldcs(&xA[f0]);
        const float2 v1 = __ldcs(&xA[f1]);
        a0.x = fmaf(wA, v0.x, a0.x); a0.y = fmaf(wA, v0.y, a0.y);
        a1.x = fmaf(wA, v1.x, a1.x); a1.y = fmaf(wA, v1.y, a1.y);
        if (has2) {
            const float2 v2 = __ldcs(&xA[f2]);
            a2.x = fmaf(wA, v2.x, a2.x); a2.y = fmaf(wA, v2.y, a2.y);
        }
    }

    uint32_t* __restrict__ outp = g_att_hl + (size_t)b * KPAD;
    store_hl(outp, f0, a0);
    store_hl(outp, f1, a1);
    if (has2) store_hl(outp, f2, a2);
}

// ---------------------------------------------------------------------------
// K2 (exact R13, measured ~51us): HMMA, smem-staged A + fragment-major B.
// ---------------------------------------------------------------------------
#define MMA16816(c0, c1, c2, c3, a0, a1, a2, a3, b0, b1) \
    asm volatile("mma.sync.aligned.m16n8k16.row.col.f32.bf16.bf16.f32 " \
        "{%0,%1,%2,%3}, {%4,%5,%6,%7}, {%8,%9}, {%0,%1,%2,%3};" \
        : "+f"(c0), "+f"(c1), "+f"(c2), "+f"(c3) \
        : "r"(a0), "r"(a1), "r"(a2), "r"(a3), "r"(b0), "r"(b1))

#define LDSM_X4(r0, r1, r2, r3, addr) \
    asm volatile("ldmatrix.sync.aligned.m8n8.x4.shared.b16 {%0,%1,%2,%3}, [%4];" \
        : "=r"(r0), "=r"(r1), "=r"(r2), "=r"(r3) : "r"(addr))

#define ROWSTRIDE 12

__global__ __launch_bounds__(256) void proj_hmma_kernel(
    const float* __restrict__ bias,
    float* __restrict__ out)
{
    __shared__ __align__(16) uint32_t sAhi[2][64 * ROWSTRIDE];
    __shared__ __align__(16) uint32_t sAlo[2][64 * ROWSTRIDE];

    const int tid  = threadIdx.x;
    const int wid  = tid >> 5;
    const int lane = tid & 31;
    const int gid  = lane >> 2;
    const int tig  = lane & 3;
    const int mg   = wid & 3;
    const int ng   = wid >> 2;

    const int m0 = blockIdx.x * 64;

    const int srow = tid >> 2;
    const int sseg = tid & 3;
    const bool sok = (m0 + srow) < NUM_BAGS;
    const uint32_t* __restrict__ aptr = g_att_hl + (size_t)(m0 + srow) * KPAD;
    const int sidx = srow * ROWSTRIDE + 2 * sseg;

    const int arow  = 16 * mg + (lane & 15);
    const int acol  = (lane < 16) ? 0 : 4;
    const uint32_t a_off = (uint32_t)(arow * ROWSTRIDE + acol) * 4u;
    const uint32_t ahi_base = smem_u32(&sAhi[0][0]);
    const uint32_t alo_base = smem_u32(&sAlo[0][0]);
    const uint32_t bufstride = 64 * ROWSTRIDE * 4u;

    float c[4][4];
    #pragma unroll
    for (int i = 0; i < 4; i++)
        #pragma unroll
        for (int q = 0; q < 4; q++) c[i][q] = 0.0f;

    {
        uint4 av = make_uint4(0, 0, 0, 0);
        if (sok) av = *(const uint4*)(aptr + 4 * sseg);
        *(uint2*)&sAhi[0][sidx] = make_uint2(av.x, av.z);
        *(uint2*)&sAlo[0][sidx] = make_uint2(av.y, av.w);
    }
    __syncthreads();

    int buf = 0;
    for (int kt = 0; kt < 44; kt++) {
        const bool more = (kt + 1 < 44);
        uint4 av = make_uint4(0, 0, 0, 0);
        if (more && sok) av = *(const uint4*)(aptr + 16 * (kt + 1) + 4 * sseg);

        uint32_t ah0, ah1, ah2, ah3, al0, al1, al2, al3;
        LDSM_X4(ah0, ah1, ah2, ah3, ahi_base + buf * bufstride + a_off);
        LDSM_X4(al0, al1, al2, al3, alo_base + buf * bufstride + a_off);

        #pragma unroll
        for (int jj = 0; jj < 4; jj++) {
            const int t = 4 * ng + jj;
            if (t < NTILES) {
                const uint4 bv = *(const uint4*)(g_rel_fr +
                    (size_t)((t * 44 + kt) * 32 + lane) * 4);
                MMA16816(c[jj][0], c[jj][1], c[jj][2], c[jj][3],
                         ah0, ah1, ah2, ah3, bv.x, bv.z);
                MMA16816(c[jj][0], c[jj][1], c[jj][2], c[jj][3],
                         ah0, ah1, ah2, ah3, bv.y, bv.w);
                MMA16816(c[jj][0], c[jj][1], c[jj][2], c[jj][3],
                         al0, al1, al2, al3, bv.x, bv.z);
            }
        }

        if (more) {
            const int nbuf = buf ^ 1;
            *(uint2*)&sAhi[nbuf][sidx] = make_uint2(av.x, av.z);
            *(uint2*)&sAlo[nbuf][sidx] = make_uint2(av.y, av.w);
        }
        __syncthreads();
        buf ^= 1;
    }

    const int r0 = m0 + mg * 16 + gid;
    const int r1 = r0 + 8;
    #pragma unroll
    for (int jj = 0; jj < 4; jj++) {
        const int t = 4 * ng + jj;
        if (t >= NTILES) continue;
        const int n = t * 8 + 2 * tig;
        const bool n0ok = (n < RR);
        const bool n1ok = (n + 1 < RR);
        const float bv0 = n0ok ? bias[n] : 0.0f;
        const float bv1 = n1ok ? bias[n + 1] : 0.0f;
        if (r0 < NUM_BAGS) {
            if (n0ok) out[(size_t)r0 * RR + n]     = c[jj][0] + bv0;
            if (n1ok) out[(size_t)r0 * RR + n + 1] = c[jj][1] + bv1;
        }
        if (r1 < NUM_BAGS) {
            if (n0ok) out[(size_t)r1 * RR + n]     = c[jj][2] + bv0;
            if (n1ok) out[(size_t)r1 * RR + n + 1] = c[jj][3] + bv1;
        }
    }
}

extern "C" void kernel_launch(void* const* d_in, const int* in_sizes, int n_in,
                              void* d_out, int out_size)
{
    const float* repre  = (const float*)d_in[0];
    const float* relmat = (const float*)d_in[1];
    const float* bias   = (const float*)d_in[2];
    const void*  scope  = d_in[3];
    const void*  labels = d_in[4];
    float* out = (float*)d_out;

    rel_prep_kernel<<<(NTILES * 44 * 32 + 127) / 128, 128>>>(relmat);
    bag_attn_kernel<<<NUM_BAGS, 128>>>(repre, relmat, scope, labels);
    proj_hmma_kernel<<<(NUM_BAGS + 63) / 64, 256>>>(bias, out);
}

// round 16
// speedup vs baseline: 2.0407x; 1.5054x over previous
#include <cuda_runtime.h>
#include <cuda_bf16.h>
#include <math.h>
#include <cstdint>

#define NN 200000
#define NUM_BAGS 25000
#define DD 690
#define D2 345          // DD/2 float2s
#define RR 53
#define MAX_BAG 256
#define KPAD 704        // DD padded to 44*16
#define NTILES 7        // ceil(53/8) n8-tiles
#define PREP_ENTRIES (NTILES * 44 * 32)   // 9856
#define PREP_CTAS ((PREP_ENTRIES + 127) / 128)  // 77

// Interleaved (hi,lo) bf16x2 storage: u32 col 2c = hi pair, 2c+1 = lo pair.
// Cols for d>=690 stay zero (static zero-init, never written).
__device__ uint32_t g_att_hl[(size_t)NUM_BAGS * KPAD];   // 70.4 MB
// B in fragment-major layout: [ntile][kt][lane][4] = {bh(p), bl(p), bh(p+4), bl(p+4)}
__device__ uint32_t g_rel_fr[(size_t)PREP_ENTRIES * 4];

__device__ __forceinline__ int sniff_is64(const void* scope)
{
    // scope row0 = (start0=0, end0>=1). int32 layout: w[1]=end0>=1 ; int64: w[1]=0
    return (((const int*)scope)[1] == 0) ? 1 : 0;
}

__device__ __forceinline__ int load_idx(const void* p, int i, int is64)
{
    return is64 ? (int)((const long long*)p)[i] : ((const int*)p)[i];
}

__device__ __forceinline__ uint32_t smem_u32(const void* p)
{
    uint32_t addr;
    asm("{ .reg .u64 tmp; cvta.to.shared.u64 tmp, %1; cvt.u32.u64 %0, tmp; }"
        : "=r"(addr) : "l"(p));
    return addr;
}

__device__ __forceinline__ void store_hl(uint32_t* __restrict__ row, int f, float2 v)
{
    __nv_bfloat16 hx = __float2bfloat16(v.x);
    __nv_bfloat16 hy = __float2bfloat16(v.y);
    __nv_bfloat16 lx = __float2bfloat16(v.x - __bfloat162float(hx));
    __nv_bfloat16 ly = __float2bfloat16(v.y - __bfloat162float(hy));
    __nv_bfloat162 hh; hh.x = hx; hh.y = hy;
    __nv_bfloat162 ll; ll.x = lx; ll.y = ly;
    row[2 * f]     = *reinterpret_cast<uint32_t*>(&hh);
    row[2 * f + 1] = *reinterpret_cast<uint32_t*>(&ll);
}

__device__ __forceinline__ uint32_t bf16x2_split_hi(float v0, float v1, uint32_t* lo)
{
    __nv_bfloat16 h0 = __float2bfloat16(v0);
    __nv_bfloat16 h1 = __float2bfloat16(v1);
    __nv_bfloat16 l0 = __float2bfloat16(v0 - __bfloat162float(h0));
    __nv_bfloat16 l1 = __float2bfloat16(v1 - __bfloat162float(h1));
    __nv_bfloat162 hh; hh.x = h0; hh.y = h1;
    __nv_bfloat162 ll; ll.x = l0; ll.y = l1;
    *lo = *reinterpret_cast<uint32_t*>(&ll);
    return *reinterpret_cast<uint32_t*>(&hh);
}

// rel prep entry (fragment-major B), executed inside K1 by the first 77 CTAs.
__device__ __forceinline__ void rel_prep_entry(const float* __restrict__ relp, int e)
{
    const int nt   = e / (44 * 32);
    const int rem  = e % (44 * 32);
    const int kt   = rem >> 5;
    const int lane = rem & 31;
    const int gid  = lane >> 2;
    const int tig  = lane & 3;
    const int n    = nt * 8 + gid;
    const int p1   = 8 * kt + tig;
    const int p2   = p1 + 4;

    float a0 = 0.0f, a1 = 0.0f, b0 = 0.0f, b1 = 0.0f;
    if (n < RR) {
        if (2 * p1 < DD)     a0 = relp[(size_t)n * DD + 2 * p1];
        if (2 * p1 + 1 < DD) a1 = relp[(size_t)n * DD + 2 * p1 + 1];
        if (2 * p2 < DD)     b0 = relp[(size_t)n * DD + 2 * p2];
        if (2 * p2 + 1 < DD) b1 = relp[(size_t)n * DD + 2 * p2 + 1];
    }
    uint32_t lo1, lo2;
    const uint32_t hi1 = bf16x2_split_hi(a0, a1, &lo1);
    const uint32_t hi2 = bf16x2_split_hi(b0, b1, &lo2);
    uint4 v; v.x = hi1; v.y = lo1; v.z = hi2; v.w = lo2;
    *reinterpret_cast<uint4*>(g_rel_fr + (size_t)e * 4) = v;
}

// ---------------------------------------------------------------------------
// K1 (exact R13 structure, measured ~137us): block per bag, 128 threads.
// First 77 CTAs also emit the fragment-major B (consumed only by K2).
// ---------------------------------------------------------------------------
__global__ __launch_bounds__(128, 10) void bag_attn_kernel(
    const float* __restrict__ repre,
    const float* __restrict__ rel,
    const void*  __restrict__ scope,
    const void*  __restrict__ labels)
{
    __shared__ float s_rl[MAX_BAG];
    __shared__ float s_w[MAX_BAG];

    const int tid  = threadIdx.x;
    const int wid  = tid >> 5;
    const int lane = tid & 31;
    const int is64 = sniff_is64(scope);

    const int b = blockIdx.x;

    // fused rel-prep (independent of bag work; K2 runs after this kernel)
    if (b < PREP_CTAS) {
        const int e = b * 128 + tid;
        if (e < PREP_ENTRIES) rel_prep_entry(rel, e);
    }

    int start = load_idx(scope, 2 * b, is64);
    int end   = load_idx(scope, 2 * b + 1, is64);
    if (start < 0) start = 0;
    if (start > NN) start = NN;
    if (end < start) end = start;
    if (end > NN) end = NN;
    int nb = end - start;
    if (nb > MAX_BAG) nb = MAX_BAG;

    int mylab = 0;
    {
        const int j = wid + 4 * lane;
        if (j < nb) {
            int lab = load_idx(labels, start + j, is64);
            if (lab < 0) lab = 0;
            if (lab >= RR) lab = RR - 1;
            mylab = lab;
        }
    }

    // ---- phase 1: per-instance logits (warp per instance, float2) ----
    for (int k = 0; ; k++) {
        const int j = wid + 4 * k;
        if (j >= nb) break;
        int lab;
        if (k < 32) {
            lab = __shfl_sync(0xffffffffu, mylab, k);
        } else {
            lab = load_idx(labels, start + j, is64);
            if (lab < 0) lab = 0;
            if (lab >= RR) lab = RR - 1;
        }
        const float2* __restrict__ xr2 = (const float2*)(repre + (size_t)(start + j) * DD);
        const float2* __restrict__ rr2 = (const float2*)(rel + (size_t)lab * DD);
        float acc = 0.0f;
        #pragma unroll
        for (int it = 0; it < 10; it++) {
            const int d = lane + 32 * it;
            const float2 x = xr2[d];
            const float2 r = rr2[d];
            acc = fmaf(x.x, r.x, acc);
            acc = fmaf(x.y, r.y, acc);
        }
        {
            const int d = 320 + lane;
            if (d < D2) {
                const float2 x = xr2[d];
                const float2 r = rr2[d];
                acc = fmaf(x.x, r.x, acc);
                acc = fmaf(x.y, r.y, acc);
            }
        }
        #pragma unroll
        for (int o = 16; o > 0; o >>= 1)
            acc += __shfl_xor_sync(0xffffffffu, acc, o);
        if (lane == 0) s_rl[j] = acc;
    }
    __syncthreads();

    // ---- phase 2: softmax ----
    const bool fast = (nb <= 32);
    float wreg = 0.0f;
    if (fast) {
        float t = (lane < nb) ? s_rl[lane] : -INFINITY;
        float m = t;
        #pragma unroll
        for (int o = 16; o > 0; o >>= 1)
            m = fmaxf(m, __shfl_xor_sync(0xffffffffu, m, o));
        float e = (lane < nb) ? expf(t - m) : 0.0f;
        float s = e;
        #pragma unroll
        for (int o = 16; o > 0; o >>= 1)
            s += __shfl_xor_sync(0xffffffffu, s, o);
        wreg = e / s;
    } else {
        if (wid == 0) {
            float m = -INFINITY;
            for (int j = lane; j < nb; j += 32) m = fmaxf(m, s_rl[j]);
            #pragma unroll
            for (int o = 16; o > 0; o >>= 1)
                m = fmaxf(m, __shfl_xor_sync(0xffffffffu, m, o));
            float s = 0.0f;
            for (int j = lane; j < nb; j += 32) {
                float e = expf(s_rl[j] - m);
                s_w[j] = e;
                s += e;
            }
            #pragma unroll
            for (int o = 16; o > 0; o >>= 1)
                s += __shfl_xor_sync(0xffffffffu, s, o);
            float inv = 1.0f / s;
            for (int j = lane; j < nb; j += 32) s_w[j] *= inv;
        }
        __syncthreads();
    }

    // ---- phase 3: weighted bag sum (3 slots/thread, unroll x4, streaming) ----
    const int f0 = tid;
    const int f1 = tid + 128;
    const int f2 = tid + 256;
    const bool has2 = (f2 < D2);
    float2 a0 = make_float2(0.0f, 0.0f);
    float2 a1 = make_float2(0.0f, 0.0f);
    float2 a2 = make_float2(0.0f, 0.0f);

    int j = 0;
    for (; j + 3 < nb; j += 4) {
        const float2* __restrict__ x0 = (const float2*)(repre + (size_t)(start + j    ) * DD);
        const float2* __restrict__ x1 = (const float2*)(repre + (size_t)(start + j + 1) * DD);
        const float2* __restrict__ x2 = (const float2*)(repre + (size_t)(start + j + 2) * DD);
        const float2* __restrict__ x3 = (const float2*)(repre + (size_t)(start + j + 3) * DD);
        float w0, w1, w2, w3;
        if (fast) {
            w0 = __shfl_sync(0xffffffffu, wreg, j & 31);
            w1 = __shfl_sync(0xffffffffu, wreg, (j + 1) & 31);
            w2 = __shfl_sync(0xffffffffu, wreg, (j + 2) & 31);
            w3 = __shfl_sync(0xffffffffu, wreg, (j + 3) & 31);
        } else {
            w0 = s_w[j]; w1 = s_w[j + 1]; w2 = s_w[j + 2]; w3 = s_w[j + 3];
        }
        const float2 p00 = __ldcs(&x0[f0]), p10 = __ldcs(&x1[f0]),
                     p20 = __ldcs(&x2[f0]), p30 = __ldcs(&x3[f0]);
        const float2 p01 = __ldcs(&x0[f1]), p11 = __ldcs(&x1[f1]),
                     p21 = __ldcs(&x2[f1]), p31 = __ldcs(&x3[f1]);
        float2 p02, p12, p22, p32;
        if (has2) { p02 = __ldcs(&x0[f2]); p12 = __ldcs(&x1[f2]);
                    p22 = __ldcs(&x2[f2]); p32 = __ldcs(&x3[f2]); }
        a0.x = fmaf(w0, p00.x, a0.x); a0.y = fmaf(w0, p00.y, a0.y);
        a0.x = fmaf(w1, p10.x, a0.x); a0.y = fmaf(w1, p10.y, a0.y);
        a0.x = fmaf(w2, p20.x, a0.x); a0.y = fmaf(w2, p20.y, a0.y);
        a0.x = fmaf(w3, p30.x, a0.x); a0.y = fmaf(w3, p30.y, a0.y);
        a1.x = fmaf(w0, p01.x, a1.x); a1.y = fmaf(w0, p01.y, a1.y);
        a1.x = fmaf(w1, p11.x, a1.x); a1.y = fmaf(w1, p11.y, a1.y);
        a1.x = fmaf(w2, p21.x, a1.x); a1.y = fmaf(w2, p21.y, a1.y);
        a1.x = fmaf(w3, p31.x, a1.x); a1.y = fmaf(w3, p31.y, a1.y);
        if (has2) {
            a2.x = fmaf(w0, p02.x, a2.x); a2.y = fmaf(w0, p02.y, a2.y);
            a2.x = fmaf(w1, p12.x, a2.x); a2.y = fmaf(w1, p12.y, a2.y);
            a2.x = fmaf(w2, p22.x, a2.x); a2.y = fmaf(w2, p22.y, a2.y);
            a2.x = fmaf(w3, p32.x, a2.x); a2.y = fmaf(w3, p32.y, a2.y);
        }
    }
    for (; j < nb; j++) {
        const float2* __restrict__ xA = (const float2*)(repre + (size_t)(start + j) * DD);
        const float wA = fast ? __shfl_sync(0xffffffffu, wreg, j & 31) : s_w[j];
        const float2 v0 = __ldcs(&xA[f0]);
        const float2 v1 = __ldcs(&xA[f1]);
        a0.x = fmaf(wA, v0.x, a0.x); a0.y = fmaf(wA, v0.y, a0.y);
        a1.x = fmaf(wA, v1.x, a1.x); a1.y = fmaf(wA, v1.y, a1.y);
        if (has2) {
            const float2 v2 = __ldcs(&xA[f2]);
            a2.x = fmaf(wA, v2.x, a2.x); a2.y = fmaf(wA, v2.y, a2.y);
        }
    }

    uint32_t* __restrict__ outp = g_att_hl + (size_t)b * KPAD;
    store_hl(outp, f0, a0);
    store_hl(outp, f1, a1);
    if (has2) store_hl(outp, f2, a2);
}

// ---------------------------------------------------------------------------
// K2 (exact R13, measured ~51us): HMMA bf16 2-split 3-term,
// smem-staged A (ldmatrix) + fragment-major B (coalesced LDG).
// ---------------------------------------------------------------------------
#define MMA16816(c0, c1, c2, c3, a0, a1, a2, a3, b0, b1) \
    asm volatile("mma.sync.aligned.m16n8k16.row.col.f32.bf16.bf16.f32 " \
        "{%0,%1,%2,%3}, {%4,%5,%6,%7}, {%8,%9}, {%0,%1,%2,%3};" \
        : "+f"(c0), "+f"(c1), "+f"(c2), "+f"(c3) \
        : "r"(a0), "r"(a1), "r"(a2), "r"(a3), "r"(b0), "r"(b1))

#define LDSM_X4(r0, r1, r2, r3, addr) \
    asm volatile("ldmatrix.sync.aligned.m8n8.x4.shared.b16 {%0,%1,%2,%3}, [%4];" \
        : "=r"(r0), "=r"(r1), "=r"(r2), "=r"(r3) : "r"(addr))

#define ROWSTRIDE 12

__global__ __launch_bounds__(256) void proj_hmma_kernel(
    const float* __restrict__ bias,
    float* __restrict__ out)
{
    __shared__ __align__(16) uint32_t sAhi[2][64 * ROWSTRIDE];
    __shared__ __align__(16) uint32_t sAlo[2][64 * ROWSTRIDE];

    const int tid  = threadIdx.x;
    const int wid  = tid >> 5;
    const int lane = tid & 31;
    const int gid  = lane >> 2;
    const int tig  = lane & 3;
    const int mg   = wid & 3;
    const int ng   = wid >> 2;

    const int m0 = blockIdx.x * 64;

    const int srow = tid >> 2;
    const int sseg = tid & 3;
    const bool sok = (m0 + srow) < NUM_BAGS;
    const uint32_t* __restrict__ aptr = g_att_hl + (size_t)(m0 + srow) * KPAD;
    const int sidx = srow * ROWSTRIDE + 2 * sseg;

    const int arow  = 16 * mg + (lane & 15);
    const int acol  = (lane < 16) ? 0 : 4;
    const uint32_t a_off = (uint32_t)(arow * ROWSTRIDE + acol) * 4u;
    const uint32_t ahi_base = smem_u32(&sAhi[0][0]);
    const uint32_t alo_base = smem_u32(&sAlo[0][0]);
    const uint32_t bufstride = 64 * ROWSTRIDE * 4u;

    float c[4][4];
    #pragma unroll
    for (int i = 0; i < 4; i++)
        #pragma unroll
        for (int q = 0; q < 4; q++) c[i][q] = 0.0f;

    {
        uint4 av = make_uint4(0, 0, 0, 0);
        if (sok) av = *(const uint4*)(aptr + 4 * sseg);
        *(uint2*)&sAhi[0][sidx] = make_uint2(av.x, av.z);
        *(uint2*)&sAlo[0][sidx] = make_uint2(av.y, av.w);
    }
    __syncthreads();

    int buf = 0;
    for (int kt = 0; kt < 44; kt++) {
        const bool more = (kt + 1 < 44);
        uint4 av = make_uint4(0, 0, 0, 0);
        if (more && sok) av = *(const uint4*)(aptr + 16 * (kt + 1) + 4 * sseg);

        uint32_t ah0, ah1, ah2, ah3, al0, al1, al2, al3;
        LDSM_X4(ah0, ah1, ah2, ah3, ahi_base + buf * bufstride + a_off);
        LDSM_X4(al0, al1, al2, al3, alo_base + buf * bufstride + a_off);

        #pragma unroll
        for (int jj = 0; jj < 4; jj++) {
            const int t = 4 * ng + jj;
            if (t < NTILES) {
                const uint4 bv = *(const uint4*)(g_rel_fr +
                    (size_t)((t * 44 + kt) * 32 + lane) * 4);
                MMA16816(c[jj][0], c[jj][1], c[jj][2], c[jj][3],
                         ah0, ah1, ah2, ah3, bv.x, bv.z);
                MMA16816(c[jj][0], c[jj][1], c[jj][2], c[jj][3],
                         ah0, ah1, ah2, ah3, bv.y, bv.w);
                MMA16816(c[jj][0], c[jj][1], c[jj][2], c[jj][3],
                         al0, al1, al2, al3, bv.x, bv.z);
            }
        }

        if (more) {
            const int nbuf = buf ^ 1;
            *(uint2*)&sAhi[nbuf][sidx] = make_uint2(av.x, av.z);
            *(uint2*)&sAlo[nbuf][sidx] = make_uint2(av.y, av.w);
        }
        __syncthreads();
        buf ^= 1;
    }

    const int r0 = m0 + mg * 16 + gid;
    const int r1 = r0 + 8;
    #pragma unroll
    for (int jj = 0; jj < 4; jj++) {
        const int t = 4 * ng + jj;
        if (t >= NTILES) continue;
        const int n = t * 8 + 2 * tig;
        const bool n0ok = (n < RR);
        const bool n1ok = (n + 1 < RR);
        const float bv0 = n0ok ? bias[n] : 0.0f;
        const float bv1 = n1ok ? bias[n + 1] : 0.0f;
        if (r0 < NUM_BAGS) {
            if (n0ok) out[(size_t)r0 * RR + n]     = c[jj][0] + bv0;
            if (n1ok) out[(size_t)r0 * RR + n + 1] = c[jj][1] + bv1;
        }
        if (r1 < NUM_BAGS) {
            if (n0ok) out[(size_t)r1 * RR + n]     = c[jj][2] + bv0;
            if (n1ok) out[(size_t)r1 * RR + n + 1] = c[jj][3] + bv1;
        }
    }
}

extern "C" void kernel_launch(void* const* d_in, const int* in_sizes, int n_in,
                              void* d_out, int out_size)
{
    const float* repre  = (const float*)d_in[0];
    const float* relmat = (const float*)d_in[1];
    const float* bias   = (const float*)d_in[2];
    const void*  scope  = d_in[3];
    const void*  labels = d_in[4];
    float* out = (float*)d_out;

    bag_attn_kernel<<<NUM_BAGS, 128>>>(repre, relmat, scope, labels);
    proj_hmma_kernel<<<(NUM_BAGS + 63) / 64, 256>>>(bias, out);
}